// round 15
// baseline (speedup 1.0000x reference)
#include <cuda_runtime.h>

#define NEMB      512
#define SBLOCKS   16
#define STHREADS  512
#define CW_PER_SB (NEMB / SBLOCKS)           // 32 codewords per sort block
#define QBLOCKS   256
#define QTHREADS  512
#define LUT_SIZE  4096
#define LUT_CHUNK (LUT_SIZE / QTHREADS)      // 8 buckets per thread
#define NGRP      8
#define GSTRIDE   32                         // 128 B between counters

__device__ float        g_sval[NEMB];
__device__ int          g_sidx[NEMB];
__device__ float        g_lossAcc[NGRP * GSTRIDE];
__device__ unsigned int g_done1[NGRP * GSTRIDE];
__device__ unsigned int g_done2;

// ---------------------------------------------------------------------------
// Kernel 1: rank-sort the codebook. 16 blocks x 512 threads; each block ranks
// 32 codewords against the smem-staged codebook. Kernel boundary = the sync.
// ---------------------------------------------------------------------------
__global__ void __launch_bounds__(STHREADS)
sort_kernel(const float* __restrict__ emb) {
    __shared__ float s_emb[NEMB];
    __shared__ int   s_rank[CW_PER_SB];

    const int tid = threadIdx.x;

    if (tid < CW_PER_SB) s_rank[tid] = 0;
    if (tid < NEMB / 4) {
        const float4 e = __ldg(&reinterpret_cast<const float4*>(emb)[tid]);
        reinterpret_cast<float4*>(s_emb)[tid] = e;
    }
    __syncthreads();

    // 16 threads per codeword, each scanning 8 float4 (32 values) via LDS.
    const int cw_local = tid >> 4;                       // 0..31
    const int cw       = blockIdx.x * CW_PER_SB + cw_local;
    const int seg      = tid & 15;
    const float cv = s_emb[cw];

    int partial = 0;
    #pragma unroll
    for (int q4 = 0; q4 < 8; q4++) {
        const int j4 = seg * 8 + q4;
        const float4 e = reinterpret_cast<const float4*>(s_emb)[j4];
        const int j = j4 * 4;
        partial += (int)(e.x < cv) + (int)((e.x == cv) && (j + 0 < cw));
        partial += (int)(e.y < cv) + (int)((e.y == cv) && (j + 1 < cw));
        partial += (int)(e.z < cv) + (int)((e.z == cv) && (j + 2 < cw));
        partial += (int)(e.w < cv) + (int)((e.w == cv) && (j + 3 < cw));
    }
    // reduce across the 16 threads sharing a codeword (they're lane-contiguous)
    #pragma unroll
    for (int off = 8; off > 0; off >>= 1)
        partial += __shfl_xor_sync(0xFFFFFFFFu, partial, off, 16);
    if (seg == 0) s_rank[cw_local] = partial;   // exact rank (keys unique)
    __syncthreads();

    if (tid < CW_PER_SB) {
        const int mycw = blockIdx.x * CW_PER_SB + tid;
        const int r = s_rank[tid];
        g_sval[r] = s_emb[mycw];
        g_sidx[r] = mycw;
    }
}

// ---------------------------------------------------------------------------
// Kernel 2: quantize. No inter-block waits on the hot path; loss finalized by
// the last-done block via 8-way-spread counters (measured cheap in R14).
// ---------------------------------------------------------------------------
__global__ void __launch_bounds__(QTHREADS, 2)
quant_kernel(const float* __restrict__ x,
             float* __restrict__ out,
             int n, int write_loss) {
    __shared__ float sval[NEMB];
    __shared__ int   sidx[NEMB];
    __shared__ short lut[LUT_SIZE];
    __shared__ float s_loss;

    const int tid = threadIdx.x;
    const int bid = blockIdx.x;
    const int grp = bid & (NGRP - 1);

    // ---- load this thread's 2 elements (overlaps codebook load) -----------
    const int c    = bid * QTHREADS + tid;
    const int base = c * 2;
    const bool full = (base + 1 < n);
    float2 v = make_float2(0.f, 0.f);
    if (full) v = *reinterpret_cast<const float2*>(x + base);

    if (tid == 0) s_loss = 0.0f;

    // ---- sorted codebook from previous kernel (coherent at launch) --------
    if (tid < NEMB / 4) {
        const float4 vv = __ldg(&reinterpret_cast<const float4*>(g_sval)[tid]);
        reinterpret_cast<float4*>(sval)[tid] = vv;
    } else if (tid < NEMB / 2) {
        const int t = tid - NEMB / 4;
        const int4 ii = __ldg(&reinterpret_cast<const int4*>(g_sidx)[t]);
        reinterpret_cast<int4*>(sidx)[t] = ii;
    }
    __syncthreads();

    // ---- build bucket LUT: lut[k] = lower_bound(sval, edge_k) -------------
    const float vmin = sval[0];
    const float vmax = sval[NEMB - 1];
    const float rng  = vmax - vmin;
    const float inv  = (rng > 0.0f) ? (float)LUT_SIZE / rng : 0.0f;
    const float step = (rng > 0.0f) ? rng / (float)LUT_SIZE : 0.0f;

    {
        const int k0 = tid * LUT_CHUNK;
        const float edge0 = vmin + (float)k0 * step;
        int lo = 0, hi = NEMB;
        #pragma unroll
        for (int it = 0; it < 10; it++) {
            const int mid = (lo + hi) >> 1;
            if (hi > lo) { if (sval[mid] < edge0) lo = mid + 1; else hi = mid; }
        }
        #pragma unroll
        for (int j = 0; j < LUT_CHUNK; j++) {
            const float edge = vmin + (float)(k0 + j) * step;
            while (lo < NEMB && sval[lo] < edge) lo++;
            lut[k0 + j] = (short)lo;
        }
    }
    __syncthreads();

    // ---- quantize ----------------------------------------------------------
    float local = 0.0f;

    if (full) {
        float vv[2] = {v.x, v.y};
        float qq[2];
        #pragma unroll
        for (int e = 0; e < 2; e++) {
            const float xv = vv[e];
            int k = (int)((xv - vmin) * inv);
            k = min(max(k - 1, 0), LUT_SIZE - 1);   // -1: margin vs fp rounding
            int lo = (int)lut[k];
            while (lo < NEMB && sval[lo] < xv) lo++;

            float q, d2;
            if (lo == 0) {
                q = sval[0];
                const float d = __fadd_rn(xv, -q);
                d2 = __fmul_rn(d, d);
            } else if (lo == NEMB) {
                q = sval[NEMB - 1];
                const float d = __fadd_rn(xv, -q);
                d2 = __fmul_rn(d, d);
            } else {
                const float a  = sval[lo - 1];
                const float b  = sval[lo];
                const float da = __fadd_rn(xv, -a);
                const float db = __fadd_rn(xv, -b);
                const float da2 = __fmul_rn(da, da);
                const float db2 = __fmul_rn(db, db);
                bool pick_a;
                if (da2 < db2)      pick_a = true;
                else if (db2 < da2) pick_a = false;
                else                pick_a = (sidx[lo - 1] < sidx[lo]);
                q  = pick_a ? a   : b;
                d2 = pick_a ? da2 : db2;
            }
            qq[e] = q;
            local += d2;
        }
        float2 o;
        o.x = qq[0]; o.y = qq[1];
        *reinterpret_cast<float2*>(out + base) = o;
    } else {
        for (int i = base; i < n && i < base + 2; i++) {
            const float xv = x[i];
            int k = (int)((xv - vmin) * inv);
            k = min(max(k - 1, 0), LUT_SIZE - 1);
            int lo = (int)lut[k];
            while (lo < NEMB && sval[lo] < xv) lo++;
            float q, d2;
            if (lo == 0) {
                q = sval[0];
                const float d = __fadd_rn(xv, -q); d2 = __fmul_rn(d, d);
            } else if (lo == NEMB) {
                q = sval[NEMB - 1];
                const float d = __fadd_rn(xv, -q); d2 = __fmul_rn(d, d);
            } else {
                const float a  = sval[lo - 1];
                const float b  = sval[lo];
                const float da = __fadd_rn(xv, -a);
                const float db = __fadd_rn(xv, -b);
                const float da2 = __fmul_rn(da, da);
                const float db2 = __fmul_rn(db, db);
                bool pick_a;
                if (da2 < db2)      pick_a = true;
                else if (db2 < da2) pick_a = false;
                else                pick_a = (sidx[lo - 1] < sidx[lo]);
                q  = pick_a ? a   : b;
                d2 = pick_a ? da2 : db2;
            }
            out[i] = q;
            local += d2;
        }
    }

    // ---- loss reduction -----------------------------------------------------
    #pragma unroll
    for (int off = 16; off > 0; off >>= 1)
        local += __shfl_xor_sync(0xFFFFFFFFu, local, off);
    if ((tid & 31) == 0)
        atomicAdd(&s_loss, local);
    __syncthreads();

    // ---- last-done block finalizes + resets counters (graph replay) -------
    if (tid == 0) {
        atomicAdd(&g_lossAcc[grp * GSTRIDE], s_loss);
        __threadfence();
        const unsigned d = atomicAdd(&g_done1[grp * GSTRIDE], 1u);
        if (d == (QBLOCKS / NGRP) - 1) {
            const unsigned d2 = atomicAdd(&g_done2, 1u);
            if (d2 == NGRP - 1) {
                float total = 0.0f;
                #pragma unroll
                for (int i = 0; i < NGRP; i++)
                    total += __ldcg(&g_lossAcc[i * GSTRIDE]);
                if (write_loss)
                    out[n] = 1.25f * total / (float)n;
                #pragma unroll
                for (int i = 0; i < NGRP; i++) {
                    g_done1[i * GSTRIDE]   = 0u;
                    g_lossAcc[i * GSTRIDE] = 0.0f;
                }
                g_done2 = 0u;
            }
        }
    }
}

extern "C" void kernel_launch(void* const* d_in, const int* in_sizes, int n_in,
                              void* d_out, int out_size) {
    const float* x   = (const float*)d_in[0];   // pre_quantized, 16*1*128*128
    const float* emb = (const float*)d_in[1];   // emb_weight, 512*1
    float* out = (float*)d_out;

    const int n = in_sizes[0];                  // 262144
    const int write_loss = (out_size > n) ? 1 : 0;

    sort_kernel<<<SBLOCKS, STHREADS>>>(emb);
    quant_kernel<<<QBLOCKS, QTHREADS>>>(x, out, n, write_loss);
}

// round 16
// speedup vs baseline: 1.1805x; 1.1805x over previous
#include <cuda_runtime.h>

#define NEMB      512
#define QBLOCKS   256
#define QTHREADS  512
#define CWPB      (NEMB / QBLOCKS)           // 2 codewords per block
#define LUT_SIZE  8192
#define LUT_CHUNK (LUT_SIZE / QTHREADS)      // 16 buckets per thread
#define NGRP      8
#define GSTRIDE   32                         // 128 B between counters

__device__ float        g_sval[NEMB];
__device__ unsigned int g_rdy1[NGRP * GSTRIDE];
__device__ unsigned int g_rdy2;
__device__ volatile unsigned int g_all_ready;
__device__ float        g_lossAcc[NGRP * GSTRIDE];
__device__ unsigned int g_done1[NGRP * GSTRIDE];
__device__ unsigned int g_done2;

// The ONE bucket map used by both LUT build and queries (fp-consistent).
__device__ __forceinline__ int bucket_of(float v, float vmin, float inv) {
    int b = (int)(__fmul_rn(__fadd_rn(v, -vmin), inv));
    return min(b, LUT_SIZE - 1);
}

__global__ void __launch_bounds__(QTHREADS, 2)
vq_fused_kernel(const float* __restrict__ x,
                const float* __restrict__ emb,
                float* __restrict__ out,
                int n, int write_loss) {
    __shared__ float s_emb[NEMB];
    __shared__ float sval[NEMB];
    __shared__ short lut[LUT_SIZE];
    __shared__ int   s_rank[CWPB];
    __shared__ float s_part[QTHREADS / 32];

    const int tid = threadIdx.x;
    const int bid = blockIdx.x;
    const int grp = bid & (NGRP - 1);

    // ---- Prefetch this thread's 2 elements (independent of codebook) ------
    const int c    = bid * QTHREADS + tid;
    const int base = c * 2;
    const bool full = (base + 1 < n);
    float2 v = make_float2(0.f, 0.f);
    if (full) v = *reinterpret_cast<const float2*>(x + base);

    // ---- Phase 1: every block rank-sorts its 2 codewords ------------------
    if (tid < CWPB) s_rank[tid] = 0;
    if (tid < NEMB / 4) {
        const float4 e = __ldg(&reinterpret_cast<const float4*>(emb)[tid]);
        reinterpret_cast<float4*>(s_emb)[tid] = e;
    }
    __syncthreads();

    {
        const int g  = tid >> 8;                         // 0..1 codeword group
        const int cw = bid * CWPB + g;                   // original index
        const int l  = tid & 255;                        // lane in group
        const float cv = s_emb[cw];
        const float2 e = reinterpret_cast<const float2*>(s_emb)[l];
        const int j = l * 2;
        int partial = 0;
        partial += (int)(e.x < cv) + (int)((e.x == cv) && (j + 0 < cw));
        partial += (int)(e.y < cv) + (int)((e.y == cv) && (j + 1 < cw));
        #pragma unroll
        for (int off = 16; off > 0; off >>= 1)
            partial += __shfl_xor_sync(0xFFFFFFFFu, partial, off);
        if ((tid & 31) == 0) atomicAdd(&s_rank[g], partial);
    }
    __syncthreads();

    if (tid < CWPB) {
        const int mycw = bid * CWPB + tid;
        const int r = s_rank[tid];             // exact permutation (keys unique)
        g_sval[r] = s_emb[mycw];
        __threadfence();                       // publish before counting ready
    }
    __syncthreads();

    // ---- Ready barrier: 8-way level-1 chains -> level-2 -> one poll word --
    if (tid == 0) {
        const unsigned r = atomicAdd(&g_rdy1[grp * GSTRIDE], 1u);
        if (r == (QBLOCKS / NGRP) - 1) {
            const unsigned r2 = atomicAdd(&g_rdy2, 1u);
            if (r2 == NGRP - 1)
                g_all_ready = 1u;
        }
        while (g_all_ready == 0u) { }          // single-word read spin
    }
    __syncthreads();

    // ---- Copy sorted codebook (L2 is the coherence point) -----------------
    if (tid < NEMB / 4) {
        const float4 vv = __ldcg(&reinterpret_cast<const float4*>(g_sval)[tid]);
        reinterpret_cast<float4*>(sval)[tid] = vv;
    }
    __syncthreads();

    const float vmin = sval[0];
    const float vmax = sval[NEMB - 1];
    const float rng  = __fadd_rn(vmax, -vmin);
    const float inv  = (rng > 0.0f) ? __fdiv_rn((float)LUT_SIZE, rng) : 0.0f;

    // ---- Build LUT: lut[k] = min{ j : bucket_of(sval[j]) >= k } ------------
    {
        const int k0 = tid * LUT_CHUNK;
        // binary search for first j with bucket(sval[j]) >= k0
        int lo = 0, hi = NEMB;
        #pragma unroll
        for (int it = 0; it < 10; it++) {
            const int mid = (lo + hi) >> 1;
            if (hi > lo) {
                if (bucket_of(sval[mid], vmin, inv) < k0) lo = mid + 1;
                else hi = mid;
            }
        }
        int curb = (lo < NEMB) ? bucket_of(sval[lo], vmin, inv) : LUT_SIZE;
        #pragma unroll
        for (int j = 0; j < LUT_CHUNK; j++) {
            const int k = k0 + j;
            while (curb < k) {
                lo++;
                curb = (lo < NEMB) ? bucket_of(sval[lo], vmin, inv) : LUT_SIZE;
            }
            lut[k] = (short)lo;
        }
    }
    __syncthreads();

    // ---- Quantize: branchless window-4 nearest -----------------------------
    float local = 0.0f;

    if (full) {
        float vv[2] = {v.x, v.y};
        float qq[2];
        #pragma unroll
        for (int e = 0; e < 2; e++) {
            const float xv = vv[e];
            int k = bucket_of(xv, vmin, inv);
            k = max(k, 0);                               // x may lie below vmin
            const int s = min(max((int)lut[k] - 1, 0), NEMB - 4);

            const float v0 = sval[s + 0];
            const float v1 = sval[s + 1];
            const float v2 = sval[s + 2];
            const float v3 = sval[s + 3];

            float q, d2;
            if (v3 < xv && s + 3 < NEMB - 1) {
                // rare: >2 codewords mapped into one bucket — scan upward
                int lo = s + 4;
                while (lo < NEMB && sval[lo] < xv) lo++;
                const float a = sval[lo - 1];
                const float b = (lo < NEMB) ? sval[lo] : a;
                const float da = __fadd_rn(xv, -a), db = __fadd_rn(xv, -b);
                const float ea = __fmul_rn(da, da), eb = __fmul_rn(db, db);
                q  = (ea <= eb) ? a : b;
                d2 = fminf(ea, eb);
            } else {
                const float d0 = __fadd_rn(xv, -v0);
                const float d1 = __fadd_rn(xv, -v1);
                const float d2_ = __fadd_rn(xv, -v2);
                const float d3 = __fadd_rn(xv, -v3);
                const float e0 = __fmul_rn(d0, d0);
                const float e1 = __fmul_rn(d1, d1);
                const float e2 = __fmul_rn(d2_, d2_);
                const float e3 = __fmul_rn(d3, d3);
                const float qa = (e0 <= e1) ? v0 : v1;
                const float ea = fminf(e0, e1);
                const float qb = (e2 <= e3) ? v2 : v3;
                const float eb = fminf(e2, e3);
                q  = (ea <= eb) ? qa : qb;
                d2 = fminf(ea, eb);
            }
            qq[e] = q;
            local += d2;
        }
        float2 o;
        o.x = qq[0]; o.y = qq[1];
        *reinterpret_cast<float2*>(out + base) = o;
    } else {
        for (int i = base; i < n && i < base + 2; i++) {
            const float xv = x[i];
            int k = bucket_of(xv, vmin, inv);
            k = max(k, 0);
            int lo = min(max((int)lut[k] - 1, 0), NEMB - 1);
            while (lo < NEMB && sval[lo] < xv) lo++;
            const float a = sval[max(lo - 1, 0)];
            const float b = sval[min(lo, NEMB - 1)];
            const float da = __fadd_rn(xv, -a), db = __fadd_rn(xv, -b);
            const float ea = __fmul_rn(da, da), eb = __fmul_rn(db, db);
            const float q = (ea <= eb) ? a : b;
            out[i] = q;
            local += fminf(ea, eb);
        }
    }

    // ---- Loss: warp shuffle -> smem array -> warp-0 reduce (no chains) ----
    #pragma unroll
    for (int off = 16; off > 0; off >>= 1)
        local += __shfl_xor_sync(0xFFFFFFFFu, local, off);
    if ((tid & 31) == 0)
        s_part[tid >> 5] = local;
    __syncthreads();

    if (tid < 32) {
        float t = (tid < QTHREADS / 32) ? s_part[tid] : 0.0f;
        #pragma unroll
        for (int off = 8; off > 0; off >>= 1)
            t += __shfl_xor_sync(0xFFFFFFFFu, t, off);

        // ---- last-done block finalizes + resets (graph replay) ------------
        if (tid == 0) {
            atomicAdd(&g_lossAcc[grp * GSTRIDE], t);
            __threadfence();
            const unsigned d = atomicAdd(&g_done1[grp * GSTRIDE], 1u);
            if (d == (QBLOCKS / NGRP) - 1) {
                const unsigned d2 = atomicAdd(&g_done2, 1u);
                if (d2 == NGRP - 1) {
                    float total = 0.0f;
                    #pragma unroll
                    for (int i = 0; i < NGRP; i++)
                        total += __ldcg(&g_lossAcc[i * GSTRIDE]);
                    if (write_loss)
                        out[n] = 1.25f * total / (float)n;
                    #pragma unroll
                    for (int i = 0; i < NGRP; i++) {
                        g_rdy1[i * GSTRIDE]    = 0u;
                        g_done1[i * GSTRIDE]   = 0u;
                        g_lossAcc[i * GSTRIDE] = 0.0f;
                    }
                    g_rdy2 = 0u;
                    g_done2 = 0u;
                    g_all_ready = 0u;
                }
            }
        }
    }
}

extern "C" void kernel_launch(void* const* d_in, const int* in_sizes, int n_in,
                              void* d_out, int out_size) {
    const float* x   = (const float*)d_in[0];   // pre_quantized, 16*1*128*128
    const float* emb = (const float*)d_in[1];   // emb_weight, 512*1
    float* out = (float*)d_out;

    const int n = in_sizes[0];                  // 262144
    const int write_loss = (out_size > n) ? 1 : 0;

    vq_fused_kernel<<<QBLOCKS, QTHREADS>>>(x, emb, out, n, write_loss);
}